// round 1
// baseline (speedup 1.0000x reference)
#include <cuda_runtime.h>

#define FULL 0xffffffffu

// ---------------- scratch (static __device__, no allocs) ----------------
// g: per (s,t) pair conv1 pre-activation contribution  [1024][4*47]
// h: per (u,v) edge contribution + bias, TRANSPOSED    [4*47][256] for coalescing
// feat: per-sample 16-dim features after conv stack    [262144][16]
// preds: per-sample MLP output                         [262144]
// part: per-block partial rbc sums                     [256][32]
__device__ __align__(16) float g_buf[1024 * 188];
__device__ __align__(16) float h_buf[188 * 256];
__device__ __align__(16) float feat_buf[262144 * 16];
__device__ __align__(16) float preds_buf[262144];
__device__ __align__(16) float part_buf[256 * 32];

// ---------------- K1: precompute g and h ----------------
__global__ void k1_pre(const float* __restrict__ emb, const int* __restrict__ edges,
                       const float* __restrict__ w1, const float* __restrict__ b1)
{
    int idx = blockIdx.x * blockDim.x + threadIdx.x;
    const int NG = 1024 * 188;
    if (idx < NG) {
        int p = idx / 188, r = idx % 188;
        int o = r / 47, j = r % 47;
        int s = p >> 5, t = p & 31;
        const float* es = emb + s * 96 + 2 * j;
        const float* et = emb + t * 96 + 2 * j;
        float v = 0.f;
        #pragma unroll
        for (int k = 0; k < 3; k++) {
            v += w1[o * 12 + 0 * 3 + k] * es[k];
            v += w1[o * 12 + 1 * 3 + k] * et[k];
        }
        g_buf[p * 188 + o * 47 + j] = v;
    } else {
        int q = idx - NG;
        if (q >= 256 * 188) return;
        int e = q / 188, r = q % 188;
        int o = r / 47, j = r % 47;
        int u = edges[2 * e], vv = edges[2 * e + 1];
        const float* eu = emb + u * 96 + 2 * j;
        const float* ev = emb + vv * 96 + 2 * j;
        float v = b1[o];
        #pragma unroll
        for (int k = 0; k < 3; k++) {
            v += w1[o * 12 + 2 * 3 + k] * eu[k];
            v += w1[o * 12 + 3 * 3 + k] * ev[k];
        }
        h_buf[(o * 47 + j) * 256 + e] = v;
    }
}

// ---------------- K2: conv2/conv3 stack -> 16 features per sample ----------------
__global__ void __launch_bounds__(128) k2_feat(
    const float* __restrict__ w2, const float* __restrict__ b2,
    const float* __restrict__ w3, const float* __restrict__ b3)
{
    int sid = blockIdx.x * blockDim.x + threadIdx.x; // 0..262143
    int p = sid >> 8, e = sid & 255;
    const float* gp = g_buf + p * 188;

    // layer1: add g+h, relu, maxpool2 -> p1[4][23]
    float p1[4][23];
    #pragma unroll
    for (int i = 0; i < 4; i++) {
        #pragma unroll
        for (int j = 0; j < 23; j++) {
            int o0 = i * 47 + 2 * j;
            float a0 = gp[o0]     + h_buf[o0 * 256 + e];
            float a1 = gp[o0 + 1] + h_buf[(o0 + 1) * 256 + e];
            p1[i][j] = fmaxf(fmaxf(a0, a1), 0.f);
        }
    }

    // conv2 (stride1) + relu + pool -> p2[4][10]
    float w2r[4][4][3], b2r[4];
    #pragma unroll
    for (int o = 0; o < 4; o++) {
        b2r[o] = b2[o];
        #pragma unroll
        for (int i = 0; i < 4; i++)
            #pragma unroll
            for (int k = 0; k < 3; k++)
                w2r[o][i][k] = w2[o * 12 + i * 3 + k];
    }
    float p2[4][10];
    #pragma unroll
    for (int m = 0; m < 10; m++) {
        #pragma unroll
        for (int o = 0; o < 4; o++) {
            float c0 = b2r[o], c1 = b2r[o];
            #pragma unroll
            for (int i = 0; i < 4; i++)
                #pragma unroll
                for (int k = 0; k < 3; k++) {
                    c0 += w2r[o][i][k] * p1[i][2 * m + k];
                    c1 += w2r[o][i][k] * p1[i][2 * m + 1 + k];
                }
            p2[o][m] = fmaxf(fmaxf(c0, c1), 0.f);
        }
    }

    // conv3 + relu + pool -> f[16] (channel-major flatten)
    float w3r[4][4][3], b3r[4];
    #pragma unroll
    for (int o = 0; o < 4; o++) {
        b3r[o] = b3[o];
        #pragma unroll
        for (int i = 0; i < 4; i++)
            #pragma unroll
            for (int k = 0; k < 3; k++)
                w3r[o][i][k] = w3[o * 12 + i * 3 + k];
    }
    float f[16];
    #pragma unroll
    for (int m = 0; m < 4; m++) {
        #pragma unroll
        for (int o = 0; o < 4; o++) {
            float c0 = b3r[o], c1 = b3r[o];
            #pragma unroll
            for (int i = 0; i < 4; i++)
                #pragma unroll
                for (int k = 0; k < 3; k++) {
                    c0 += w3r[o][i][k] * p2[i][2 * m + k];
                    c1 += w3r[o][i][k] * p2[i][2 * m + 1 + k];
                }
            f[o * 4 + m] = fmaxf(fmaxf(c0, c1), 0.f);
        }
    }

    float4* fp = (float4*)(feat_buf + (size_t)sid * 16);
    fp[0] = make_float4(f[0],  f[1],  f[2],  f[3]);
    fp[1] = make_float4(f[4],  f[5],  f[6],  f[7]);
    fp[2] = make_float4(f[8],  f[9],  f[10], f[11]);
    fp[3] = make_float4(f[12], f[13], f[14], f[15]);
}

// ---------------- K3: fused fc1..fc4 MLP, 4 samples per warp ----------------
__global__ void __launch_bounds__(128) k3_mlp(
    const float* __restrict__ fc1_w, const float* __restrict__ fc1_b,
    const float* __restrict__ fc2_w, const float* __restrict__ fc2_b,
    const float* __restrict__ fc3_w, const float* __restrict__ fc3_b,
    const float* __restrict__ fc4_w, const float* __restrict__ fc4_b)
{
    int lane = threadIdx.x & 31;
    int wid  = threadIdx.x >> 5;
    int wg   = blockIdx.x * 4 + wid;   // 0..65535
    int sid0 = wg * 4;
    int p = sid0 >> 8;
    int s = p >> 5, t = p & 31;

    // ---- fc1: z1[i][r] = output m = r*32+lane for sample i ----
    float z1[4][4];
    {
        float fa[4][16];
        #pragma unroll
        for (int i = 0; i < 4; i++) {
            const float4* fp4 = (const float4*)(feat_buf + (size_t)(sid0 + i) * 16);
            #pragma unroll
            for (int q = 0; q < 4; q++) {
                float4 v = fp4[q];
                fa[i][q * 4 + 0] = v.x; fa[i][q * 4 + 1] = v.y;
                fa[i][q * 4 + 2] = v.z; fa[i][q * 4 + 3] = v.w;
            }
        }
        #pragma unroll
        for (int i = 0; i < 4; i++)
            #pragma unroll
            for (int r = 0; r < 4; r++)
                z1[i][r] = fc1_b[r * 32 + lane];
        #pragma unroll
        for (int ff = 0; ff < 16; ff++) {
            float wa = fc1_w[ff * 128 +  0 + lane];
            float wb = fc1_w[ff * 128 + 32 + lane];
            float wc = fc1_w[ff * 128 + 64 + lane];
            float wd = fc1_w[ff * 128 + 96 + lane];
            #pragma unroll
            for (int i = 0; i < 4; i++) {
                z1[i][0] += fa[i][ff] * wa;
                z1[i][1] += fa[i][ff] * wb;
                z1[i][2] += fa[i][ff] * wc;
                z1[i][3] += fa[i][ff] * wd;
            }
        }
        #pragma unroll
        for (int i = 0; i < 4; i++)
            #pragma unroll
            for (int r = 0; r < 4; r++)
                z1[i][r] = fmaxf(z1[i][r], 0.f);
    }

    // ---- fc2: z2[i][jj] = output n = lane*8+jj ----
    float z2[4][8];
    {
        float4 bA = *(const float4*)(fc2_b + lane * 8);
        float4 bB = *(const float4*)(fc2_b + lane * 8 + 4);
        #pragma unroll
        for (int i = 0; i < 4; i++) {
            z2[i][0] = bA.x; z2[i][1] = bA.y; z2[i][2] = bA.z; z2[i][3] = bA.w;
            z2[i][4] = bB.x; z2[i][5] = bB.y; z2[i][6] = bB.z; z2[i][7] = bB.w;
        }
    }
    #pragma unroll
    for (int kk = 0; kk < 4; kk++) {
        const float* wp = fc2_w + (size_t)(kk * 32) * 256 + lane * 8;
        for (int l = 0; l < 32; l++) {          // k = kk*32 + l
            float4 wA = *(const float4*)wp;
            float4 wB = *(const float4*)(wp + 4);
            float zk[4];
            zk[0] = __shfl_sync(FULL, z1[0][kk], l);
            zk[1] = __shfl_sync(FULL, z1[1][kk], l);
            zk[2] = __shfl_sync(FULL, z1[2][kk], l);
            zk[3] = __shfl_sync(FULL, z1[3][kk], l);
            #pragma unroll
            for (int i = 0; i < 4; i++) {
                z2[i][0] += zk[i] * wA.x; z2[i][1] += zk[i] * wA.y;
                z2[i][2] += zk[i] * wA.z; z2[i][3] += zk[i] * wA.w;
                z2[i][4] += zk[i] * wB.x; z2[i][5] += zk[i] * wB.y;
                z2[i][6] += zk[i] * wB.z; z2[i][7] += zk[i] * wB.w;
            }
            wp += 256;
        }
    }
    #pragma unroll
    for (int i = 0; i < 4; i++)
        #pragma unroll
        for (int jj = 0; jj < 8; jj++)
            z2[i][jj] = fmaxf(z2[i][jj], 0.f);

    // ---- fc3: z3[i][jj] = output n = lane*4+jj ----
    float z3[4][4];
    {
        float4 b3v = *(const float4*)(fc3_b + lane * 4);
        #pragma unroll
        for (int i = 0; i < 4; i++) {
            z3[i][0] = b3v.x; z3[i][1] = b3v.y; z3[i][2] = b3v.z; z3[i][3] = b3v.w;
        }
    }
    for (int src = 0; src < 32; src++) {
        #pragma unroll
        for (int r = 0; r < 8; r++) {           // k = src*8 + r
            const float4 w = *(const float4*)(fc3_w + (size_t)(src * 8 + r) * 128 + lane * 4);
            float zk[4];
            zk[0] = __shfl_sync(FULL, z2[0][r], src);
            zk[1] = __shfl_sync(FULL, z2[1][r], src);
            zk[2] = __shfl_sync(FULL, z2[2][r], src);
            zk[3] = __shfl_sync(FULL, z2[3][r], src);
            #pragma unroll
            for (int i = 0; i < 4; i++) {
                z3[i][0] += zk[i] * w.x; z3[i][1] += zk[i] * w.y;
                z3[i][2] += zk[i] * w.z; z3[i][3] += zk[i] * w.w;
            }
        }
    }
    #pragma unroll
    for (int i = 0; i < 4; i++)
        #pragma unroll
        for (int jj = 0; jj < 4; jj++)
            z3[i][jj] = fmaxf(z3[i][jj], 0.f);

    // ---- fc4 + mask + store ----
    float4 w4 = *(const float4*)(fc4_w + lane * 4);
    float b4 = fc4_b[0];
    float mask = (s != t) ? 1.f : 0.f;
    #pragma unroll
    for (int i = 0; i < 4; i++) {
        float v = z3[i][0] * w4.x + z3[i][1] * w4.y + z3[i][2] * w4.z + z3[i][3] * w4.w;
        #pragma unroll
        for (int off = 16; off; off >>= 1)
            v += __shfl_xor_sync(FULL, v, off);
        if (lane == 0)
            preds_buf[sid0 + i] = (v + b4) * mask;
    }
}

// ---------------- K4: 3-step propagation, one warp per pair p ----------------
__global__ void __launch_bounds__(128) k4_prop(const int* __restrict__ edges)
{
    __shared__ int us[256], vs[256];
    __shared__ float wsum[4][32];
    int tid = threadIdx.x, lane = tid & 31, wid = tid >> 5;
    for (int i = tid; i < 256; i += 128) {
        us[i] = edges[2 * i];
        vs[i] = edges[2 * i + 1];
    }
    __syncthreads();

    int p = blockIdx.x * 4 + wid;
    int s = p >> 5;
    float pr[8];
    #pragma unroll
    for (int kk = 0; kk < 8; kk++)
        pr[kk] = preds_buf[p * 256 + kk * 32 + lane];

    float x = (lane == s) ? 1.f : 0.f;
    float racc = 0.f;
    for (int step = 0; step < 3; step++) {
        float xn = 0.f;
        #pragma unroll
        for (int kk = 0; kk < 8; kk++) {
            for (int l = 0; l < 32; l++) {
                int e = kk * 32 + l;
                float prv = __shfl_sync(FULL, pr[kk], l);
                float xu  = __shfl_sync(FULL, x, us[e]);
                xn += (vs[e] == lane) ? prv * xu : 0.f;
            }
        }
        x = xn;
        racc += x;
    }
    wsum[wid][lane] = racc;
    __syncthreads();
    if (tid < 32)
        part_buf[blockIdx.x * 32 + tid] =
            wsum[0][tid] + wsum[1][tid] + wsum[2][tid] + wsum[3][tid];
}

// ---------------- K5: final reduce + normalize ----------------
__global__ void k5_norm(float* __restrict__ out)
{
    int lane = threadIdx.x;
    float ssum = 0.f;
    for (int b = 0; b < 256; b++)
        ssum += part_buf[b * 32 + lane];
    float tot = ssum;
    #pragma unroll
    for (int off = 16; off; off >>= 1)
        tot += __shfl_xor_sync(FULL, tot, off);
    out[lane] = ssum / tot;
}

// ---------------- launch ----------------
extern "C" void kernel_launch(void* const* d_in, const int* in_sizes, int n_in,
                              void* d_out, int out_size)
{
    const float* emb   = (const float*)d_in[0];
    const int*   edges = (const int*)d_in[1];
    const float* w1 = (const float*)d_in[2];  const float* b1 = (const float*)d_in[3];
    const float* w2 = (const float*)d_in[4];  const float* b2 = (const float*)d_in[5];
    const float* w3 = (const float*)d_in[6];  const float* b3 = (const float*)d_in[7];
    const float* f1w = (const float*)d_in[8];  const float* f1b = (const float*)d_in[9];
    const float* f2w = (const float*)d_in[10]; const float* f2b = (const float*)d_in[11];
    const float* f3w = (const float*)d_in[12]; const float* f3b = (const float*)d_in[13];
    const float* f4w = (const float*)d_in[14]; const float* f4b = (const float*)d_in[15];
    float* out = (float*)d_out;

    k1_pre<<<1880, 128>>>(emb, edges, w1, b1);          // (1024+256)*188 work items
    k2_feat<<<2048, 128>>>(w2, b2, w3, b3);             // 262144 samples, 1 thread each
    k3_mlp<<<16384, 128>>>(f1w, f1b, f2w, f2b, f3w, f3b, f4w, f4b); // 65536 warps * 4 samples
    k4_prop<<<256, 128>>>(edges);                       // 1024 warps, 1 pair each
    k5_norm<<<1, 32>>>(out);
}

// round 5
// speedup vs baseline: 8.2656x; 8.2656x over previous
#include <cuda_runtime.h>
#include <cuda_fp16.h>
#include <cstdint>

#define FULL 0xffffffffu

// ---------------- scratch (static __device__, no allocs) ----------------
__device__ __align__(16) float g_buf[1024 * 188];
__device__ __align__(16) float h_buf[188 * 256];
__device__ __align__(16) float feat_buf[262144 * 16];
__device__ __align__(16) float preds_buf[262144];
__device__ __align__(16) float part_buf[256 * 32];

// ---------------- K1: precompute g and h ----------------
__global__ void k1_pre(const float* __restrict__ emb, const int* __restrict__ edges,
                       const float* __restrict__ w1, const float* __restrict__ b1)
{
    int idx = blockIdx.x * blockDim.x + threadIdx.x;
    const int NG = 1024 * 188;
    if (idx < NG) {
        int p = idx / 188, r = idx % 188;
        int o = r / 47, j = r % 47;
        int s = p >> 5, t = p & 31;
        const float* es = emb + s * 96 + 2 * j;
        const float* et = emb + t * 96 + 2 * j;
        float v = 0.f;
        #pragma unroll
        for (int k = 0; k < 3; k++) {
            v += w1[o * 12 + 0 * 3 + k] * es[k];
            v += w1[o * 12 + 1 * 3 + k] * et[k];
        }
        g_buf[p * 188 + o * 47 + j] = v;
    } else {
        int q = idx - NG;
        if (q >= 256 * 188) return;
        int e = q / 188, r = q % 188;
        int o = r / 47, j = r % 47;
        int u = edges[2 * e], vv = edges[2 * e + 1];
        const float* eu = emb + u * 96 + 2 * j;
        const float* ev = emb + vv * 96 + 2 * j;
        float v = b1[o];
        #pragma unroll
        for (int k = 0; k < 3; k++) {
            v += w1[o * 12 + 2 * 3 + k] * eu[k];
            v += w1[o * 12 + 3 * 3 + k] * ev[k];
        }
        h_buf[(o * 47 + j) * 256 + e] = v;
    }
}

// ---------------- K2: conv2/conv3 stack -> 16 features per sample ----------------
__global__ void __launch_bounds__(128) k2_feat(
    const float* __restrict__ w2, const float* __restrict__ b2,
    const float* __restrict__ w3, const float* __restrict__ b3)
{
    int sid = blockIdx.x * blockDim.x + threadIdx.x;
    int p = sid >> 8, e = sid & 255;
    const float* gp = g_buf + p * 188;

    float p1[4][23];
    #pragma unroll
    for (int i = 0; i < 4; i++) {
        #pragma unroll
        for (int j = 0; j < 23; j++) {
            int o0 = i * 47 + 2 * j;
            float a0 = gp[o0]     + h_buf[o0 * 256 + e];
            float a1 = gp[o0 + 1] + h_buf[(o0 + 1) * 256 + e];
            p1[i][j] = fmaxf(fmaxf(a0, a1), 0.f);
        }
    }

    float w2r[4][4][3], b2r[4];
    #pragma unroll
    for (int o = 0; o < 4; o++) {
        b2r[o] = b2[o];
        #pragma unroll
        for (int i = 0; i < 4; i++)
            #pragma unroll
            for (int k = 0; k < 3; k++)
                w2r[o][i][k] = w2[o * 12 + i * 3 + k];
    }
    float p2[4][10];
    #pragma unroll
    for (int m = 0; m < 10; m++) {
        #pragma unroll
        for (int o = 0; o < 4; o++) {
            float c0 = b2r[o], c1 = b2r[o];
            #pragma unroll
            for (int i = 0; i < 4; i++)
                #pragma unroll
                for (int k = 0; k < 3; k++) {
                    c0 += w2r[o][i][k] * p1[i][2 * m + k];
                    c1 += w2r[o][i][k] * p1[i][2 * m + 1 + k];
                }
            p2[o][m] = fmaxf(fmaxf(c0, c1), 0.f);
        }
    }

    float w3r[4][4][3], b3r[4];
    #pragma unroll
    for (int o = 0; o < 4; o++) {
        b3r[o] = b3[o];
        #pragma unroll
        for (int i = 0; i < 4; i++)
            #pragma unroll
            for (int k = 0; k < 3; k++)
                w3r[o][i][k] = w3[o * 12 + i * 3 + k];
    }
    float f[16];
    #pragma unroll
    for (int m = 0; m < 4; m++) {
        #pragma unroll
        for (int o = 0; o < 4; o++) {
            float c0 = b3r[o], c1 = b3r[o];
            #pragma unroll
            for (int i = 0; i < 4; i++)
                #pragma unroll
                for (int k = 0; k < 3; k++) {
                    c0 += w3r[o][i][k] * p2[i][2 * m + k];
                    c1 += w3r[o][i][k] * p2[i][2 * m + 1 + k];
                }
            f[o * 4 + m] = fmaxf(fmaxf(c0, c1), 0.f);
        }
    }

    float4* fp = (float4*)(feat_buf + (size_t)sid * 16);
    fp[0] = make_float4(f[0],  f[1],  f[2],  f[3]);
    fp[1] = make_float4(f[4],  f[5],  f[6],  f[7]);
    fp[2] = make_float4(f[8],  f[9],  f[10], f[11]);
    fp[3] = make_float4(f[12], f[13], f[14], f[15]);
}

// ================= K3: fused HMMA fp16 MLP (mma.sync.m16n8k16) =================
// SMEM: B-fragment-prepacked weights + biases.
//   OFF_B1: fc1 [1kt][16nt]  frags: 16*32*8   = 4KB
//   OFF_B2: fc2 [8kt][32nt]  frags: 256*32*8  = 64KB
//   OFF_B3: fc3 [16kt][16nt] frags: 256*32*8  = 64KB
//   OFF_BIAS: floats b1[128] b2[256] b3[128] w4[128] b4
static constexpr int OFF_B1 = 0;
static constexpr int OFF_B2 = 4096;
static constexpr int OFF_B3 = OFF_B2 + 65536;
static constexpr int OFF_BIAS = OFF_B3 + 65536;
static constexpr int K3_SMEM = OFF_BIAS + 644 * 4;

__device__ __forceinline__ void mma16816(float& c0, float& c1, float& c2, float& c3,
                                         uint32_t a0, uint32_t a1, uint32_t a2, uint32_t a3,
                                         uint32_t b0, uint32_t b1)
{
    asm volatile(
        "mma.sync.aligned.m16n8k16.row.col.f32.f16.f16.f32 "
        "{%0,%1,%2,%3}, {%4,%5,%6,%7}, {%8,%9}, {%0,%1,%2,%3};"
        : "+f"(c0), "+f"(c1), "+f"(c2), "+f"(c3)
        : "r"(a0), "r"(a1), "r"(a2), "r"(a3), "r"(b0), "r"(b1));
}

__device__ __forceinline__ uint32_t packh2(float x, float y)
{
    __half2 h = __floats2half2_rn(x, y);
    return *(uint32_t*)&h;
}

// Stage W[K][N] (row-major fp32) into B-fragment layout.
// frag(kt,nt), lane l = 4*g + t:  .x = h2(W[kt*16+2t][nt*8+g], W[..+1][..]),
//                                 .y = h2(W[kt*16+2t+8][..], W[..+9][..])
__device__ __forceinline__ void stage_w(char* smem, int dst, const float* __restrict__ src,
                                        int K, int N, int NT, int tid)
{
    for (int idx = tid; idx < K * N; idx += 256) {
        int k = idx / N, n = idx - k * N;
        int kt = k >> 4, kk = k & 15;
        int t = (kk & 7) >> 1, g = n & 7, nt = n >> 3;
        int lane = g * 4 + t;
        int frag = kt * NT + nt;
        int byte = (frag * 32 + lane) * 8 + ((kk >> 3) & 1) * 4 + (kk & 1) * 2;
        *(__half*)(smem + dst + byte) = __float2half(src[idx]);
    }
}

__global__ void __launch_bounds__(256, 1) k3_mma(
    const float* __restrict__ f1w, const float* __restrict__ f1b,
    const float* __restrict__ f2w, const float* __restrict__ f2b,
    const float* __restrict__ f3w, const float* __restrict__ f3b,
    const float* __restrict__ f4w, const float* __restrict__ f4b)
{
    extern __shared__ char smem[];
    int tid = threadIdx.x;
    int warp = tid >> 5, lane = tid & 31;
    int g = lane >> 2, t = lane & 3;

    // ---- stage weights & biases ----
    stage_w(smem, OFF_B1, f1w,  16, 128, 16, tid);
    stage_w(smem, OFF_B2, f2w, 128, 256, 32, tid);
    stage_w(smem, OFF_B3, f3w, 256, 128, 16, tid);
    float* bias = (float*)(smem + OFF_BIAS);
    if (tid < 128) {
        bias[tid]       = f1b[tid];   // b1
        bias[384 + tid] = f3b[tid];   // b3
        bias[512 + tid] = f4w[tid];   // w4
    }
    if (tid < 256) bias[128 + tid] = f2b[tid];  // b2
    if (tid == 0)  bias[640] = f4b[0];
    __syncthreads();

    const uint2* B1f = (const uint2*)(smem + OFF_B1);
    const uint2* B2f = (const uint2*)(smem + OFF_B2);
    const uint2* B3f = (const uint2*)(smem + OFF_B3);
    const float* b1s = bias;
    const float* b2s = bias + 128;
    const float* b3s = bias + 384;
    const float* w4s = bias + 512;
    float b4 = bias[640];

    for (int tile = blockIdx.x; tile < 2048; tile += gridDim.x) {
        int base = tile * 128 + warp * 16;
        int p = tile >> 1;
        float mask = ((p >> 5) != (p & 31)) ? 1.f : 0.f;

        // ---- A1 fragment from feats (fp32 -> fp16) ----
        int row0 = base + g, row1 = row0 + 8;
        const float2* fr0 = (const float2*)(feat_buf + (size_t)row0 * 16);
        const float2* fr1 = (const float2*)(feat_buf + (size_t)row1 * 16);
        float2 q0 = fr0[t], q1 = fr1[t], q2 = fr0[t + 4], q3 = fr1[t + 4];
        uint32_t a1f[4];
        a1f[0] = packh2(q0.x, q0.y);
        a1f[1] = packh2(q1.x, q1.y);
        a1f[2] = packh2(q2.x, q2.y);
        a1f[3] = packh2(q3.x, q3.y);

        // ---- fc1: 16 ntiles -> A2 frags (8 ktiles) ----
        uint32_t A2[8][4];
        uint32_t e0 = 0, e1 = 0;
        #pragma unroll
        for (int nt = 0; nt < 16; nt++) {
            const float2 bb = *(const float2*)(b1s + nt * 8 + 2 * t);
            float c0 = bb.x, c1 = bb.y, c2 = bb.x, c3 = bb.y;
            uint2 B = B1f[nt * 32 + lane];
            mma16816(c0, c1, c2, c3, a1f[0], a1f[1], a1f[2], a1f[3], B.x, B.y);
            uint32_t p0 = packh2(fmaxf(c0, 0.f), fmaxf(c1, 0.f));
            uint32_t p1 = packh2(fmaxf(c2, 0.f), fmaxf(c3, 0.f));
            if (nt & 1) {
                A2[nt >> 1][0] = e0; A2[nt >> 1][1] = e1;
                A2[nt >> 1][2] = p0; A2[nt >> 1][3] = p1;
            } else { e0 = p0; e1 = p1; }
        }

        // ---- fc2: 32 ntiles, K=128 -> A3 frags (16 ktiles) ----
        uint32_t A3[16][4];
        #pragma unroll
        for (int nt = 0; nt < 32; nt++) {
            const float2 bb = *(const float2*)(b2s + nt * 8 + 2 * t);
            float c0 = bb.x, c1 = bb.y, c2 = bb.x, c3 = bb.y;
            #pragma unroll
            for (int kt = 0; kt < 8; kt++) {
                uint2 B = B2f[(kt * 32 + nt) * 32 + lane];
                mma16816(c0, c1, c2, c3, A2[kt][0], A2[kt][1], A2[kt][2], A2[kt][3], B.x, B.y);
            }
            uint32_t p0 = packh2(fmaxf(c0, 0.f), fmaxf(c1, 0.f));
            uint32_t p1 = packh2(fmaxf(c2, 0.f), fmaxf(c3, 0.f));
            if (nt & 1) {
                A3[nt >> 1][0] = e0; A3[nt >> 1][1] = e1;
                A3[nt >> 1][2] = p0; A3[nt >> 1][3] = p1;
            } else { e0 = p0; e1 = p1; }
        }

        // ---- fc3 + fc4: 16 ntiles, K=256, fused row-dot with w4 ----
        float rs0 = 0.f, rs1 = 0.f;
        for (int nt = 0; nt < 16; nt++) {
            const float2 bb = *(const float2*)(b3s + nt * 8 + 2 * t);
            float c0 = bb.x, c1 = bb.y, c2 = bb.x, c3 = bb.y;
            #pragma unroll
            for (int kt = 0; kt < 16; kt++) {
                uint2 B = B3f[(kt * 16 + nt) * 32 + lane];
                mma16816(c0, c1, c2, c3, A3[kt][0], A3[kt][1], A3[kt][2], A3[kt][3], B.x, B.y);
            }
            const float2 wv = *(const float2*)(w4s + nt * 8 + 2 * t);
            rs0 += fmaxf(c0, 0.f) * wv.x + fmaxf(c1, 0.f) * wv.y;
            rs1 += fmaxf(c2, 0.f) * wv.x + fmaxf(c3, 0.f) * wv.y;
        }
        // reduce over the 4 lanes sharing row g
        rs0 += __shfl_xor_sync(FULL, rs0, 1);
        rs0 += __shfl_xor_sync(FULL, rs0, 2);
        rs1 += __shfl_xor_sync(FULL, rs1, 1);
        rs1 += __shfl_xor_sync(FULL, rs1, 2);
        if (t == 0) {
            preds_buf[base + g]     = (rs0 + b4) * mask;
            preds_buf[base + g + 8] = (rs1 + b4) * mask;
        }
    }
}

// ---------------- K4: 3-step propagation via dense 32x32 W per pair ----------------
__global__ void __launch_bounds__(128) k4_prop(const int* __restrict__ edges)
{
    __shared__ int us[256], vs[256];
    __shared__ float W[4][32][32];
    __shared__ float wsum[4][32];
    int tid = threadIdx.x, lane = tid & 31, wid = tid >> 5;
    for (int i = tid; i < 256; i += 128) {
        us[i] = edges[2 * i];
        vs[i] = edges[2 * i + 1];
    }
    __syncthreads();

    int p = blockIdx.x * 4 + wid;
    int s = p >> 5;
    float pr[8];
    #pragma unroll
    for (int kk = 0; kk < 8; kk++)
        pr[kk] = preds_buf[p * 256 + kk * 32 + lane];

    #pragma unroll
    for (int u = 0; u < 32; u++) W[wid][u][lane] = 0.f;
    __syncwarp();
    // deterministic owner-lane scatter: lane v accumulates W[u][v]
    #pragma unroll
    for (int i = 0; i < 8; i++) {
        for (int l = 0; l < 32; l++) {
            int e = i * 32 + l;
            float prv = __shfl_sync(FULL, pr[i], l);
            int u = us[e], v = vs[e];
            if (v == lane) W[wid][u][lane] += prv;
        }
    }
    __syncwarp();

    float x = (lane == s) ? 1.f : 0.f;
    float racc = 0.f;
    for (int step = 0; step < 3; step++) {
        float xn = 0.f;
        #pragma unroll
        for (int u = 0; u < 32; u++)
            xn += W[wid][u][lane] * __shfl_sync(FULL, x, u);
        x = xn;
        racc += x;
    }
    wsum[wid][lane] = racc;
    __syncthreads();
    if (tid < 32)
        part_buf[blockIdx.x * 32 + tid] =
            wsum[0][tid] + wsum[1][tid] + wsum[2][tid] + wsum[3][tid];
}

// ---------------- K5: final reduce + normalize ----------------
__global__ void k5_norm(float* __restrict__ out)
{
    int lane = threadIdx.x;
    float ssum = 0.f;
    for (int b = 0; b < 256; b++)
        ssum += part_buf[b * 32 + lane];
    float tot = ssum;
    #pragma unroll
    for (int off = 16; off; off >>= 1)
        tot += __shfl_xor_sync(FULL, tot, off);
    out[lane] = ssum / tot;
}

// ---------------- launch ----------------
extern "C" void kernel_launch(void* const* d_in, const int* in_sizes, int n_in,
                              void* d_out, int out_size)
{
    const float* emb   = (const float*)d_in[0];
    const int*   edges = (const int*)d_in[1];
    const float* w1 = (const float*)d_in[2];  const float* b1 = (const float*)d_in[3];
    const float* w2 = (const float*)d_in[4];  const float* b2 = (const float*)d_in[5];
    const float* w3 = (const float*)d_in[6];  const float* b3 = (const float*)d_in[7];
    const float* f1w = (const float*)d_in[8];  const float* f1b = (const float*)d_in[9];
    const float* f2w = (const float*)d_in[10]; const float* f2b = (const float*)d_in[11];
    const float* f3w = (const float*)d_in[12]; const float* f3b = (const float*)d_in[13];
    const float* f4w = (const float*)d_in[14]; const float* f4b = (const float*)d_in[15];
    float* out = (float*)d_out;

    cudaFuncSetAttribute(k3_mma, cudaFuncAttributeMaxDynamicSharedMemorySize, K3_SMEM);

    k1_pre<<<1880, 128>>>(emb, edges, w1, b1);
    k2_feat<<<2048, 128>>>(w2, b2, w3, b3);
    k3_mma<<<148, 256, K3_SMEM>>>(f1w, f1b, f2w, f2b, f3w, f3b, f4w, f4b);
    k4_prop<<<256, 128>>>(edges);
    k5_norm<<<1, 32>>>(out);
}

// round 7
// speedup vs baseline: 9.2591x; 1.1202x over previous
#include <cuda_runtime.h>
#include <cuda_fp16.h>
#include <cstdint>

#define FULL 0xffffffffu

// ---------------- scratch (static __device__, no allocs) ----------------
// g2: per-pair conv1 contribution, pair-packed: [1024][4*23 half2]  (j,j+1 pooling pair)
// h2: per-edge contribution + bias, pair-packed, edge-major: [4*23][256] half2
// feat_h: per-sample 16 fp16 features
__device__ __align__(16) __half g2_buf[1024 * 184];
__device__ __align__(16) __half h2_buf[92 * 256 * 2];
__device__ __align__(16) __half feat_h[262144 * 16];
__device__ __align__(16) float  preds_buf[262144];
__device__ __align__(16) float  part_buf[1024 * 32];

// ---------------- K1: precompute g and h (fp16, pair-packed) ----------------
__global__ void k1_pre(const float* __restrict__ emb, const int* __restrict__ edges,
                       const float* __restrict__ w1, const float* __restrict__ b1)
{
    int idx = blockIdx.x * blockDim.x + threadIdx.x;
    const int NG = 1024 * 188;
    if (idx < NG) {
        int p = idx / 188, r = idx % 188;
        int o = r / 47, j = r % 47;
        if (j >= 46) return;                      // row 46 never pooled
        int s = p >> 5, t = p & 31;
        const float* es = emb + s * 96 + 2 * j;
        const float* et = emb + t * 96 + 2 * j;
        float v = 0.f;
        #pragma unroll
        for (int k = 0; k < 3; k++) {
            v += w1[o * 12 + 0 * 3 + k] * es[k];
            v += w1[o * 12 + 1 * 3 + k] * et[k];
        }
        g2_buf[p * 184 + (o * 23 + (j >> 1)) * 2 + (j & 1)] = __float2half(v);
    } else {
        int q = idx - NG;
        if (q >= 256 * 188) return;
        int e = q / 188, r = q % 188;
        int o = r / 47, j = r % 47;
        if (j >= 46) return;
        int u = edges[2 * e], vv = edges[2 * e + 1];
        const float* eu = emb + u * 96 + 2 * j;
        const float* ev = emb + vv * 96 + 2 * j;
        float v = b1[o];
        #pragma unroll
        for (int k = 0; k < 3; k++) {
            v += w1[o * 12 + 2 * 3 + k] * eu[k];
            v += w1[o * 12 + 3 * 3 + k] * ev[k];
        }
        h2_buf[((o * 23 + (j >> 1)) * 256 + e) * 2 + (j & 1)] = __float2half(v);
    }
}

// ---------------- K2: conv2/conv3 stack -> 16 fp16 features ----------------
__global__ void __launch_bounds__(128) k2_feat(
    const float* __restrict__ w2, const float* __restrict__ b2,
    const float* __restrict__ w3, const float* __restrict__ b3)
{
    int sid = blockIdx.x * blockDim.x + threadIdx.x;
    int p = sid >> 8, e = sid & 255;
    const uint32_t* gp = (const uint32_t*)(g2_buf + p * 184);
    const uint32_t* hp = (const uint32_t*)h2_buf;

    float p1[4][23];
    #pragma unroll
    for (int i = 0; i < 4; i++) {
        #pragma unroll
        for (int j = 0; j < 23; j++) {
            int r = i * 23 + j;
            uint32_t gu = gp[r];
            uint32_t hu = hp[r * 256 + e];
            __half2 gv = *(__half2*)&gu, hv = *(__half2*)&hu;
            float a0 = __half2float(gv.x) + __half2float(hv.x);
            float a1 = __half2float(gv.y) + __half2float(hv.y);
            p1[i][j] = fmaxf(fmaxf(a0, a1), 0.f);
        }
    }

    float w2r[4][4][3], b2r[4];
    #pragma unroll
    for (int o = 0; o < 4; o++) {
        b2r[o] = b2[o];
        #pragma unroll
        for (int i = 0; i < 4; i++)
            #pragma unroll
            for (int k = 0; k < 3; k++)
                w2r[o][i][k] = w2[o * 12 + i * 3 + k];
    }
    float p2[4][10];
    #pragma unroll
    for (int m = 0; m < 10; m++) {
        #pragma unroll
        for (int o = 0; o < 4; o++) {
            float c0 = b2r[o], c1 = b2r[o];
            #pragma unroll
            for (int i = 0; i < 4; i++)
                #pragma unroll
                for (int k = 0; k < 3; k++) {
                    c0 += w2r[o][i][k] * p1[i][2 * m + k];
                    c1 += w2r[o][i][k] * p1[i][2 * m + 1 + k];
                }
            p2[o][m] = fmaxf(fmaxf(c0, c1), 0.f);
        }
    }

    float w3r[4][4][3], b3r[4];
    #pragma unroll
    for (int o = 0; o < 4; o++) {
        b3r[o] = b3[o];
        #pragma unroll
        for (int i = 0; i < 4; i++)
            #pragma unroll
            for (int k = 0; k < 3; k++)
                w3r[o][i][k] = w3[o * 12 + i * 3 + k];
    }
    uint32_t pk[8];
    #pragma unroll
    for (int m = 0; m < 4; m++) {
        #pragma unroll
        for (int o = 0; o < 4; o++) {
            float c0 = b3r[o], c1 = b3r[o];
            #pragma unroll
            for (int i = 0; i < 4; i++)
                #pragma unroll
                for (int k = 0; k < 3; k++) {
                    c0 += w3r[o][i][k] * p2[i][2 * m + k];
                    c1 += w3r[o][i][k] * p2[i][2 * m + 1 + k];
                }
            float fv = fmaxf(fmaxf(c0, c1), 0.f);
            // feature index o*4+m; pack pairs (2q,2q+1)
            int fi = o * 4 + m;
            ((__half*)pk)[fi] = __float2half(fv);
        }
    }
    uint4* fp = (uint4*)(feat_h + (size_t)sid * 16);
    fp[0] = make_uint4(pk[0], pk[1], pk[2], pk[3]);
    fp[1] = make_uint4(pk[4], pk[5], pk[6], pk[7]);
}

// ================= K3: fused HMMA fp16 MLP (mma.sync.m16n8k16) =================
static constexpr int OFF_B1 = 0;
static constexpr int OFF_B2 = 4096;
static constexpr int OFF_B3 = OFF_B2 + 65536;
static constexpr int OFF_BIAS = OFF_B3 + 65536;
static constexpr int K3_SMEM = OFF_BIAS + 644 * 4;

__device__ __forceinline__ void mma16816(float& c0, float& c1, float& c2, float& c3,
                                         uint32_t a0, uint32_t a1, uint32_t a2, uint32_t a3,
                                         uint32_t b0, uint32_t b1)
{
    asm volatile(
        "mma.sync.aligned.m16n8k16.row.col.f32.f16.f16.f32 "
        "{%0,%1,%2,%3}, {%4,%5,%6,%7}, {%8,%9}, {%0,%1,%2,%3};"
        : "+f"(c0), "+f"(c1), "+f"(c2), "+f"(c3)
        : "r"(a0), "r"(a1), "r"(a2), "r"(a3), "r"(b0), "r"(b1));
}

__device__ __forceinline__ uint32_t packh2(float x, float y)
{
    __half2 h = __floats2half2_rn(x, y);
    return *(uint32_t*)&h;
}

__device__ __forceinline__ void stage_w(char* smem, int dst, const float* __restrict__ src,
                                        int K, int N, int NT, int tid)
{
    for (int idx = tid; idx < K * N; idx += 256) {
        int k = idx / N, n = idx - k * N;
        int kt = k >> 4, kk = k & 15;
        int t = (kk & 7) >> 1, g = n & 7, nt = n >> 3;
        int lane = g * 4 + t;
        int frag = kt * NT + nt;
        int byte = (frag * 32 + lane) * 8 + ((kk >> 3) & 1) * 4 + (kk & 1) * 2;
        *(__half*)(smem + dst + byte) = __float2half(src[idx]);
    }
}

__global__ void __launch_bounds__(256, 1) k3_mma(
    const float* __restrict__ f1w, const float* __restrict__ f1b,
    const float* __restrict__ f2w, const float* __restrict__ f2b,
    const float* __restrict__ f3w, const float* __restrict__ f3b,
    const float* __restrict__ f4w, const float* __restrict__ f4b)
{
    extern __shared__ char smem[];
    int tid = threadIdx.x;
    int warp = tid >> 5, lane = tid & 31;
    int g = lane >> 2, t = lane & 3;

    stage_w(smem, OFF_B1, f1w,  16, 128, 16, tid);
    stage_w(smem, OFF_B2, f2w, 128, 256, 32, tid);
    stage_w(smem, OFF_B3, f3w, 256, 128, 16, tid);
    float* bias = (float*)(smem + OFF_BIAS);
    if (tid < 128) {
        bias[tid]       = f1b[tid];
        bias[384 + tid] = f3b[tid];
        bias[512 + tid] = f4w[tid];
    }
    if (tid < 256) bias[128 + tid] = f2b[tid];
    if (tid == 0)  bias[640] = f4b[0];
    __syncthreads();

    const uint2* B1f = (const uint2*)(smem + OFF_B1);
    const uint2* B2f = (const uint2*)(smem + OFF_B2);
    const uint2* B3f = (const uint2*)(smem + OFF_B3);
    const float* b1s = bias;
    const float* b2s = bias + 128;
    const float* b3s = bias + 384;
    const float* w4s = bias + 512;
    float b4 = bias[640];

    for (int tile = blockIdx.x; tile < 2048; tile += gridDim.x) {
        int base = tile * 128 + warp * 16;
        int p = tile >> 1;
        float mask = ((p >> 5) != (p & 31)) ? 1.f : 0.f;

        // ---- A1 fragment: direct fp16 loads ----
        int row0 = base + g, row1 = row0 + 8;
        const uint32_t* f0 = (const uint32_t*)(feat_h + (size_t)row0 * 16);
        const uint32_t* f1 = (const uint32_t*)(feat_h + (size_t)row1 * 16);
        uint32_t a1f[4];
        a1f[0] = f0[t];
        a1f[1] = f1[t];
        a1f[2] = f0[t + 4];
        a1f[3] = f1[t + 4];

        // ---- fc1 ----
        uint32_t A2[8][4];
        uint32_t e0 = 0, e1 = 0;
        #pragma unroll
        for (int nt = 0; nt < 16; nt++) {
            const float2 bb = *(const float2*)(b1s + nt * 8 + 2 * t);
            float c0 = bb.x, c1 = bb.y, c2 = bb.x, c3 = bb.y;
            uint2 B = B1f[nt * 32 + lane];
            mma16816(c0, c1, c2, c3, a1f[0], a1f[1], a1f[2], a1f[3], B.x, B.y);
            uint32_t p0 = packh2(fmaxf(c0, 0.f), fmaxf(c1, 0.f));
            uint32_t p1 = packh2(fmaxf(c2, 0.f), fmaxf(c3, 0.f));
            if (nt & 1) {
                A2[nt >> 1][0] = e0; A2[nt >> 1][1] = e1;
                A2[nt >> 1][2] = p0; A2[nt >> 1][3] = p1;
            } else { e0 = p0; e1 = p1; }
        }

        // ---- fc2 ----
        uint32_t A3[16][4];
        #pragma unroll
        for (int nt = 0; nt < 32; nt++) {
            const float2 bb = *(const float2*)(b2s + nt * 8 + 2 * t);
            float c0 = bb.x, c1 = bb.y, c2 = bb.x, c3 = bb.y;
            #pragma unroll
            for (int kt = 0; kt < 8; kt++) {
                uint2 B = B2f[(kt * 32 + nt) * 32 + lane];
                mma16816(c0, c1, c2, c3, A2[kt][0], A2[kt][1], A2[kt][2], A2[kt][3], B.x, B.y);
            }
            uint32_t p0 = packh2(fmaxf(c0, 0.f), fmaxf(c1, 0.f));
            uint32_t p1 = packh2(fmaxf(c2, 0.f), fmaxf(c3, 0.f));
            if (nt & 1) {
                A3[nt >> 1][0] = e0; A3[nt >> 1][1] = e1;
                A3[nt >> 1][2] = p0; A3[nt >> 1][3] = p1;
            } else { e0 = p0; e1 = p1; }
        }

        // ---- fc3 + fc4 ----
        float rs0 = 0.f, rs1 = 0.f;
        for (int nt = 0; nt < 16; nt++) {
            const float2 bb = *(const float2*)(b3s + nt * 8 + 2 * t);
            float c0 = bb.x, c1 = bb.y, c2 = bb.x, c3 = bb.y;
            #pragma unroll
            for (int kt = 0; kt < 16; kt++) {
                uint2 B = B3f[(kt * 16 + nt) * 32 + lane];
                mma16816(c0, c1, c2, c3, A3[kt][0], A3[kt][1], A3[kt][2], A3[kt][3], B.x, B.y);
            }
            const float2 wv = *(const float2*)(w4s + nt * 8 + 2 * t);
            rs0 += fmaxf(c0, 0.f) * wv.x + fmaxf(c1, 0.f) * wv.y;
            rs1 += fmaxf(c2, 0.f) * wv.x + fmaxf(c3, 0.f) * wv.y;
        }
        rs0 += __shfl_xor_sync(FULL, rs0, 1);
        rs0 += __shfl_xor_sync(FULL, rs0, 2);
        rs1 += __shfl_xor_sync(FULL, rs1, 1);
        rs1 += __shfl_xor_sync(FULL, rs1, 2);
        if (t == 0) {
            preds_buf[base + g]     = (rs0 + b4) * mask;
            preds_buf[base + g + 8] = (rs1 + b4) * mask;
        }
    }
}

// ---------------- K4: one block per pair; 4 warps split the edge scatter ----------------
__global__ void __launch_bounds__(128) k4_prop(const int* __restrict__ edges)
{
    __shared__ float W4[4][32][32];
    __shared__ int us[256], vs[256];
    int tid = threadIdx.x, lane = tid & 31, wid = tid >> 5;
    for (int i = tid; i < 256; i += 128) {
        us[i] = edges[2 * i];
        vs[i] = edges[2 * i + 1];
    }
    int p = blockIdx.x;
    float pr0 = preds_buf[p * 256 + wid * 64 + lane];
    float pr1 = preds_buf[p * 256 + wid * 64 + 32 + lane];
    #pragma unroll
    for (int u = 0; u < 32; u++) W4[wid][u][lane] = 0.f;
    __syncthreads();

    // each warp scatters its 64 edges into its private W copy (deterministic)
    #pragma unroll
    for (int l = 0; l < 32; l++) {
        int e = wid * 64 + l;
        float prv = __shfl_sync(FULL, pr0, l);
        if (vs[e] == lane) W4[wid][us[e]][lane] += prv;
    }
    #pragma unroll
    for (int l = 0; l < 32; l++) {
        int e = wid * 64 + 32 + l;
        float prv = __shfl_sync(FULL, pr1, l);
        if (vs[e] == lane) W4[wid][us[e]][lane] += prv;
    }
    __syncthreads();

    // fixed-order reduce of the 4 copies
    float* w0 = (float*)W4[0];
    for (int idx = tid; idx < 1024; idx += 128)
        w0[idx] = w0[idx] + ((float*)W4[1])[idx] + ((float*)W4[2])[idx] + ((float*)W4[3])[idx];
    __syncthreads();

    if (wid == 0) {
        int s = p >> 5;
        float x = (lane == s) ? 1.f : 0.f;
        float racc = 0.f;
        for (int step = 0; step < 3; step++) {
            float xn = 0.f;
            #pragma unroll
            for (int u = 0; u < 32; u++)
                xn += W4[0][u][lane] * __shfl_sync(FULL, x, u);
            x = xn;
            racc += x;
        }
        part_buf[p * 32 + lane] = racc;
    }
}

// ---------------- K5: final reduce + normalize ----------------
__global__ void __launch_bounds__(1024) k5_norm(float* __restrict__ out)
{
    __shared__ float red[32][33];
    int tid = threadIdx.x, lane = tid & 31, wid = tid >> 5;
    float ssum = 0.f;
    for (int b = wid; b < 1024; b += 32)
        ssum += part_buf[b * 32 + lane];
    red[wid][lane] = ssum;
    __syncthreads();
    if (tid < 32) {
        float v = 0.f;
        #pragma unroll
        for (int w = 0; w < 32; w++)
            v += red[w][tid];
        float tot = v;
        #pragma unroll
        for (int off = 16; off; off >>= 1)
            tot += __shfl_xor_sync(FULL, tot, off);
        out[tid] = v / tot;
    }
}

// ---------------- launch ----------------
extern "C" void kernel_launch(void* const* d_in, const int* in_sizes, int n_in,
                              void* d_out, int out_size)
{
    const float* emb   = (const float*)d_in[0];
    const int*   edges = (const int*)d_in[1];
    const float* w1 = (const float*)d_in[2];  const float* b1 = (const float*)d_in[3];
    const float* w2 = (const float*)d_in[4];  const float* b2 = (const float*)d_in[5];
    const float* w3 = (const float*)d_in[6];  const float* b3 = (const float*)d_in[7];
    const float* f1w = (const float*)d_in[8];  const float* f1b = (const float*)d_in[9];
    const float* f2w = (const float*)d_in[10]; const float* f2b = (const float*)d_in[11];
    const float* f3w = (const float*)d_in[12]; const float* f3b = (const float*)d_in[13];
    const float* f4w = (const float*)d_in[14]; const float* f4b = (const float*)d_in[15];
    float* out = (float*)d_out;

    cudaFuncSetAttribute(k3_mma, cudaFuncAttributeMaxDynamicSharedMemorySize, K3_SMEM);

    k1_pre<<<1880, 128>>>(emb, edges, w1, b1);
    k2_feat<<<2048, 128>>>(w2, b2, w3, b3);
    k3_mma<<<148, 256, K3_SMEM>>>(f1w, f1b, f2w, f2b, f3w, f3b, f4w, f4b);
    k4_prop<<<1024, 128>>>(edges);
    k5_norm<<<1, 1024>>>(out);
}

// round 8
// speedup vs baseline: 9.4215x; 1.0175x over previous
#include <cuda_runtime.h>
#include <cuda_fp16.h>
#include <cstdint>

#define FULL 0xffffffffu

// ---------------- scratch (static __device__, no allocs) ----------------
__device__ __align__(16) __half g2_buf[1024 * 184];
__device__ __align__(16) __half h2_buf[92 * 256 * 2];
__device__ __align__(16) __half feat_h[262144 * 16];
__device__ __align__(16) float  preds_buf[262144];
__device__ __align__(16) float  part_buf[1024 * 32];

// ---------------- K1: precompute g and h (fp16, pair-packed) ----------------
__global__ void k1_pre(const float* __restrict__ emb, const int* __restrict__ edges,
                       const float* __restrict__ w1, const float* __restrict__ b1)
{
    int idx = blockIdx.x * blockDim.x + threadIdx.x;
    const int NG = 1024 * 188;
    if (idx < NG) {
        int p = idx / 188, r = idx % 188;
        int o = r / 47, j = r % 47;
        if (j >= 46) return;
        int s = p >> 5, t = p & 31;
        const float* es = emb + s * 96 + 2 * j;
        const float* et = emb + t * 96 + 2 * j;
        float v = 0.f;
        #pragma unroll
        for (int k = 0; k < 3; k++) {
            v += w1[o * 12 + 0 * 3 + k] * es[k];
            v += w1[o * 12 + 1 * 3 + k] * et[k];
        }
        g2_buf[p * 184 + (o * 23 + (j >> 1)) * 2 + (j & 1)] = __float2half(v);
    } else {
        int q = idx - NG;
        if (q >= 256 * 188) return;
        int e = q / 188, r = q % 188;
        int o = r / 47, j = r % 47;
        if (j >= 46) return;
        int u = edges[2 * e], vv = edges[2 * e + 1];
        const float* eu = emb + u * 96 + 2 * j;
        const float* ev = emb + vv * 96 + 2 * j;
        float v = b1[o];
        #pragma unroll
        for (int k = 0; k < 3; k++) {
            v += w1[o * 12 + 2 * 3 + k] * eu[k];
            v += w1[o * 12 + 3 * 3 + k] * ev[k];
        }
        h2_buf[((o * 23 + (j >> 1)) * 256 + e) * 2 + (j & 1)] = __float2half(v);
    }
}

// ---------------- K2: conv2/conv3 stack -> 16 fp16 features ----------------
__global__ void __launch_bounds__(128) k2_feat(
    const float* __restrict__ w2, const float* __restrict__ b2,
    const float* __restrict__ w3, const float* __restrict__ b3)
{
    int sid = blockIdx.x * blockDim.x + threadIdx.x;
    int p = sid >> 8, e = sid & 255;
    const uint32_t* gp = (const uint32_t*)(g2_buf + p * 184);
    const uint32_t* hp = (const uint32_t*)h2_buf;

    float p1[4][23];
    #pragma unroll
    for (int i = 0; i < 4; i++) {
        #pragma unroll
        for (int j = 0; j < 23; j++) {
            int r = i * 23 + j;
            uint32_t gu = gp[r];
            uint32_t hu = hp[r * 256 + e];
            __half2 gv = *(__half2*)&gu, hv = *(__half2*)&hu;
            float a0 = __half2float(gv.x) + __half2float(hv.x);
            float a1 = __half2float(gv.y) + __half2float(hv.y);
            p1[i][j] = fmaxf(fmaxf(a0, a1), 0.f);
        }
    }

    float w2r[4][4][3], b2r[4];
    #pragma unroll
    for (int o = 0; o < 4; o++) {
        b2r[o] = b2[o];
        #pragma unroll
        for (int i = 0; i < 4; i++)
            #pragma unroll
            for (int k = 0; k < 3; k++)
                w2r[o][i][k] = w2[o * 12 + i * 3 + k];
    }
    float p2[4][10];
    #pragma unroll
    for (int m = 0; m < 10; m++) {
        #pragma unroll
        for (int o = 0; o < 4; o++) {
            float c0 = b2r[o], c1 = b2r[o];
            #pragma unroll
            for (int i = 0; i < 4; i++)
                #pragma unroll
                for (int k = 0; k < 3; k++) {
                    c0 += w2r[o][i][k] * p1[i][2 * m + k];
                    c1 += w2r[o][i][k] * p1[i][2 * m + 1 + k];
                }
            p2[o][m] = fmaxf(fmaxf(c0, c1), 0.f);
        }
    }

    float w3r[4][4][3], b3r[4];
    #pragma unroll
    for (int o = 0; o < 4; o++) {
        b3r[o] = b3[o];
        #pragma unroll
        for (int i = 0; i < 4; i++)
            #pragma unroll
            for (int k = 0; k < 3; k++)
                w3r[o][i][k] = w3[o * 12 + i * 3 + k];
    }
    uint32_t pk[8];
    #pragma unroll
    for (int m = 0; m < 4; m++) {
        #pragma unroll
        for (int o = 0; o < 4; o++) {
            float c0 = b3r[o], c1 = b3r[o];
            #pragma unroll
            for (int i = 0; i < 4; i++)
                #pragma unroll
                for (int k = 0; k < 3; k++) {
                    c0 += w3r[o][i][k] * p2[i][2 * m + k];
                    c1 += w3r[o][i][k] * p2[i][2 * m + 1 + k];
                }
            float fv = fmaxf(fmaxf(c0, c1), 0.f);
            int fi = o * 4 + m;
            ((__half*)pk)[fi] = __float2half(fv);
        }
    }
    uint4* fp = (uint4*)(feat_h + (size_t)sid * 16);
    fp[0] = make_uint4(pk[0], pk[1], pk[2], pk[3]);
    fp[1] = make_uint4(pk[4], pk[5], pk[6], pk[7]);
}

// ================= K3: fused HMMA fp16 MLP, 2 M-tiles per warp =================
static constexpr int OFF_B1 = 0;
static constexpr int OFF_B2 = 4096;
static constexpr int OFF_B3 = OFF_B2 + 65536;
static constexpr int OFF_BIAS = OFF_B3 + 65536;
static constexpr int K3_SMEM = OFF_BIAS + 644 * 4;

__device__ __forceinline__ void mma16816(float& c0, float& c1, float& c2, float& c3,
                                         uint32_t a0, uint32_t a1, uint32_t a2, uint32_t a3,
                                         uint32_t b0, uint32_t b1)
{
    asm volatile(
        "mma.sync.aligned.m16n8k16.row.col.f32.f16.f16.f32 "
        "{%0,%1,%2,%3}, {%4,%5,%6,%7}, {%8,%9}, {%0,%1,%2,%3};"
        : "+f"(c0), "+f"(c1), "+f"(c2), "+f"(c3)
        : "r"(a0), "r"(a1), "r"(a2), "r"(a3), "r"(b0), "r"(b1));
}

__device__ __forceinline__ uint32_t packh2(float x, float y)
{
    __half2 h = __floats2half2_rn(x, y);
    return *(uint32_t*)&h;
}

__device__ __forceinline__ void stage_w(char* smem, int dst, const float* __restrict__ src,
                                        int K, int N, int NT, int tid)
{
    for (int idx = tid; idx < K * N; idx += 256) {
        int k = idx / N, n = idx - k * N;
        int kt = k >> 4, kk = k & 15;
        int t = (kk & 7) >> 1, g = n & 7, nt = n >> 3;
        int lane = g * 4 + t;
        int frag = kt * NT + nt;
        int byte = (frag * 32 + lane) * 8 + ((kk >> 3) & 1) * 4 + (kk & 1) * 2;
        *(__half*)(smem + dst + byte) = __float2half(src[idx]);
    }
}

__global__ void __launch_bounds__(256, 1) k3_mma(
    const float* __restrict__ f1w, const float* __restrict__ f1b,
    const float* __restrict__ f2w, const float* __restrict__ f2b,
    const float* __restrict__ f3w, const float* __restrict__ f3b,
    const float* __restrict__ f4w, const float* __restrict__ f4b)
{
    extern __shared__ char smem[];
    int tid = threadIdx.x;
    int warp = tid >> 5, lane = tid & 31;
    int g = lane >> 2, t = lane & 3;

    stage_w(smem, OFF_B1, f1w,  16, 128, 16, tid);
    stage_w(smem, OFF_B2, f2w, 128, 256, 32, tid);
    stage_w(smem, OFF_B3, f3w, 256, 128, 16, tid);
    float* bias = (float*)(smem + OFF_BIAS);
    if (tid < 128) {
        bias[tid]       = f1b[tid];
        bias[384 + tid] = f3b[tid];
        bias[512 + tid] = f4w[tid];
    }
    if (tid < 256) bias[128 + tid] = f2b[tid];
    if (tid == 0)  bias[640] = f4b[0];
    __syncthreads();

    const uint2* B1f = (const uint2*)(smem + OFF_B1);
    const uint2* B2f = (const uint2*)(smem + OFF_B2);
    const uint2* B3f = (const uint2*)(smem + OFF_B3);
    const float* b1s = bias;
    const float* b2s = bias + 128;
    const float* b3s = bias + 384;
    const float* w4s = bias + 512;
    float b4 = bias[640];

    // tile == pair p; each warp owns 32 rows (two m16 blocks) -> B frag reused x2
    for (int p = blockIdx.x; p < 1024; p += gridDim.x) {
        int base = p * 256 + warp * 32;
        float mask = ((p >> 5) != (p & 31)) ? 1.f : 0.f;

        // ---- A1 fragments for both row blocks ----
        const uint32_t* f0 = (const uint32_t*)(feat_h + (size_t)(base + g) * 16);
        const uint32_t* f1 = (const uint32_t*)(feat_h + (size_t)(base + g + 8) * 16);
        const uint32_t* f2 = (const uint32_t*)(feat_h + (size_t)(base + g + 16) * 16);
        const uint32_t* f3 = (const uint32_t*)(feat_h + (size_t)(base + g + 24) * 16);
        uint32_t aA[4], aB[4];
        aA[0] = f0[t]; aA[1] = f1[t]; aA[2] = f0[t + 4]; aA[3] = f1[t + 4];
        aB[0] = f2[t]; aB[1] = f3[t]; aB[2] = f2[t + 4]; aB[3] = f3[t + 4];

        // ---- fc1: 16 ntiles -> A2 frags (8 ktiles) x 2 blocks ----
        uint32_t A2a[8][4], A2b[8][4];
        uint32_t ea0, ea1, eb0, eb1;
        #pragma unroll
        for (int nt = 0; nt < 16; nt++) {
            const float2 bb = *(const float2*)(b1s + nt * 8 + 2 * t);
            uint2 B = B1f[nt * 32 + lane];
            float c0 = bb.x, c1 = bb.y, c2 = bb.x, c3 = bb.y;
            mma16816(c0, c1, c2, c3, aA[0], aA[1], aA[2], aA[3], B.x, B.y);
            float d0 = bb.x, d1 = bb.y, d2 = bb.x, d3 = bb.y;
            mma16816(d0, d1, d2, d3, aB[0], aB[1], aB[2], aB[3], B.x, B.y);
            uint32_t pa0 = packh2(fmaxf(c0, 0.f), fmaxf(c1, 0.f));
            uint32_t pa1 = packh2(fmaxf(c2, 0.f), fmaxf(c3, 0.f));
            uint32_t pb0 = packh2(fmaxf(d0, 0.f), fmaxf(d1, 0.f));
            uint32_t pb1 = packh2(fmaxf(d2, 0.f), fmaxf(d3, 0.f));
            if (nt & 1) {
                A2a[nt >> 1][0] = ea0; A2a[nt >> 1][1] = ea1;
                A2a[nt >> 1][2] = pa0; A2a[nt >> 1][3] = pa1;
                A2b[nt >> 1][0] = eb0; A2b[nt >> 1][1] = eb1;
                A2b[nt >> 1][2] = pb0; A2b[nt >> 1][3] = pb1;
            } else { ea0 = pa0; ea1 = pa1; eb0 = pb0; eb1 = pb1; }
        }

        // ---- fc2: 32 ntiles, K=128 -> A3 frags (16 ktiles) x 2 blocks ----
        uint32_t A3a[16][4], A3b[16][4];
        #pragma unroll
        for (int nt = 0; nt < 32; nt++) {
            const float2 bb = *(const float2*)(b2s + nt * 8 + 2 * t);
            float c0 = bb.x, c1 = bb.y, c2 = bb.x, c3 = bb.y;
            float d0 = bb.x, d1 = bb.y, d2 = bb.x, d3 = bb.y;
            #pragma unroll
            for (int kt = 0; kt < 8; kt++) {
                uint2 B = B2f[(kt * 32 + nt) * 32 + lane];
                mma16816(c0, c1, c2, c3, A2a[kt][0], A2a[kt][1], A2a[kt][2], A2a[kt][3], B.x, B.y);
                mma16816(d0, d1, d2, d3, A2b[kt][0], A2b[kt][1], A2b[kt][2], A2b[kt][3], B.x, B.y);
            }
            uint32_t pa0 = packh2(fmaxf(c0, 0.f), fmaxf(c1, 0.f));
            uint32_t pa1 = packh2(fmaxf(c2, 0.f), fmaxf(c3, 0.f));
            uint32_t pb0 = packh2(fmaxf(d0, 0.f), fmaxf(d1, 0.f));
            uint32_t pb1 = packh2(fmaxf(d2, 0.f), fmaxf(d3, 0.f));
            if (nt & 1) {
                A3a[nt >> 1][0] = ea0; A3a[nt >> 1][1] = ea1;
                A3a[nt >> 1][2] = pa0; A3a[nt >> 1][3] = pa1;
                A3b[nt >> 1][0] = eb0; A3b[nt >> 1][1] = eb1;
                A3b[nt >> 1][2] = pb0; A3b[nt >> 1][3] = pb1;
            } else { ea0 = pa0; ea1 = pa1; eb0 = pb0; eb1 = pb1; }
        }

        // ---- fc3 + fc4: 16 ntiles, K=256, fused w4 dot, 2 blocks ----
        float rsA0 = 0.f, rsA1 = 0.f, rsB0 = 0.f, rsB1 = 0.f;
        for (int nt = 0; nt < 16; nt++) {
            const float2 bb = *(const float2*)(b3s + nt * 8 + 2 * t);
            float c0 = bb.x, c1 = bb.y, c2 = bb.x, c3 = bb.y;
            float d0 = bb.x, d1 = bb.y, d2 = bb.x, d3 = bb.y;
            #pragma unroll
            for (int kt = 0; kt < 16; kt++) {
                uint2 B = B3f[(kt * 16 + nt) * 32 + lane];
                mma16816(c0, c1, c2, c3, A3a[kt][0], A3a[kt][1], A3a[kt][2], A3a[kt][3], B.x, B.y);
                mma16816(d0, d1, d2, d3, A3b[kt][0], A3b[kt][1], A3b[kt][2], A3b[kt][3], B.x, B.y);
            }
            const float2 wv = *(const float2*)(w4s + nt * 8 + 2 * t);
            rsA0 += fmaxf(c0, 0.f) * wv.x + fmaxf(c1, 0.f) * wv.y;
            rsA1 += fmaxf(c2, 0.f) * wv.x + fmaxf(c3, 0.f) * wv.y;
            rsB0 += fmaxf(d0, 0.f) * wv.x + fmaxf(d1, 0.f) * wv.y;
            rsB1 += fmaxf(d2, 0.f) * wv.x + fmaxf(d3, 0.f) * wv.y;
        }
        rsA0 += __shfl_xor_sync(FULL, rsA0, 1); rsA0 += __shfl_xor_sync(FULL, rsA0, 2);
        rsA1 += __shfl_xor_sync(FULL, rsA1, 1); rsA1 += __shfl_xor_sync(FULL, rsA1, 2);
        rsB0 += __shfl_xor_sync(FULL, rsB0, 1); rsB0 += __shfl_xor_sync(FULL, rsB0, 2);
        rsB1 += __shfl_xor_sync(FULL, rsB1, 1); rsB1 += __shfl_xor_sync(FULL, rsB1, 2);
        if (t == 0) {
            preds_buf[base + g]      = (rsA0 + b4) * mask;
            preds_buf[base + g + 8]  = (rsA1 + b4) * mask;
            preds_buf[base + g + 16] = (rsB0 + b4) * mask;
            preds_buf[base + g + 24] = (rsB1 + b4) * mask;
        }
    }
}

// ---------------- K4: one block per pair; 8 warps, parallel matvec ----------------
__global__ void __launch_bounds__(256) k4_prop(const int* __restrict__ edges)
{
    __shared__ float W8[8][32][32];
    __shared__ int us[256], vs[256];
    __shared__ float xs[32], red[8][32];
    int tid = threadIdx.x, lane = tid & 31, wid = tid >> 5;
    if (tid < 256) {
        us[tid] = edges[2 * tid];
        vs[tid] = edges[2 * tid + 1];
    }
    int p = blockIdx.x;
    float pr = preds_buf[p * 256 + wid * 32 + lane];
    #pragma unroll
    for (int u = 0; u < 32; u++) W8[wid][u][lane] = 0.f;
    int s = p >> 5;
    if (tid < 32) xs[tid] = (tid == s) ? 1.f : 0.f;
    __syncthreads();

    // each warp scatters its 32 edges into its private W copy (deterministic)
    #pragma unroll
    for (int l = 0; l < 32; l++) {
        int e = wid * 32 + l;
        float prv = __shfl_sync(FULL, pr, l);
        if (vs[e] == lane) W8[wid][us[e]][lane] += prv;
    }
    __syncthreads();

    // fixed-order reduce of the 8 copies into W8[0]
    for (int idx = tid; idx < 1024; idx += 256) {
        float v = ((float*)W8[0])[idx];
        #pragma unroll
        for (int c = 1; c < 8; c++) v += ((float*)W8[c])[idx];
        ((float*)W8[0])[idx] = v;
    }
    __syncthreads();

    // 3-step matvec, parallel across 256 threads: thread handles 4 u's for column v
    float racc = 0.f;
    #pragma unroll
    for (int step = 0; step < 3; step++) {
        float part = 0.f;
        #pragma unroll
        for (int j = 0; j < 4; j++)
            part += W8[0][wid * 4 + j][lane] * xs[wid * 4 + j];
        red[wid][lane] = part;
        __syncthreads();
        if (tid < 32) {
            float xn = red[0][tid];
            #pragma unroll
            for (int c = 1; c < 8; c++) xn += red[c][tid];
            xs[tid] = xn;
        }
        __syncthreads();
        if (tid < 32) racc += xs[tid];
    }
    if (tid < 32) part_buf[p * 32 + tid] = racc;
}

// ---------------- K5: final reduce + normalize ----------------
__global__ void __launch_bounds__(1024) k5_norm(float* __restrict__ out)
{
    __shared__ float red[32][33];
    int tid = threadIdx.x, lane = tid & 31, wid = tid >> 5;
    float ssum = 0.f;
    for (int b = wid; b < 1024; b += 32)
        ssum += part_buf[b * 32 + lane];
    red[wid][lane] = ssum;
    __syncthreads();
    if (tid < 32) {
        float v = 0.f;
        #pragma unroll
        for (int w = 0; w < 32; w++)
            v += red[w][tid];
        float tot = v;
        #pragma unroll
        for (int off = 16; off; off >>= 1)
            tot += __shfl_xor_sync(FULL, tot, off);
        out[tid] = v / tot;
    }
}

// ---------------- launch ----------------
extern "C" void kernel_launch(void* const* d_in, const int* in_sizes, int n_in,
                              void* d_out, int out_size)
{
    const float* emb   = (const float*)d_in[0];
    const int*   edges = (const int*)d_in[1];
    const float* w1 = (const float*)d_in[2];  const float* b1 = (const float*)d_in[3];
    const float* w2 = (const float*)d_in[4];  const float* b2 = (const float*)d_in[5];
    const float* w3 = (const float*)d_in[6];  const float* b3 = (const float*)d_in[7];
    const float* f1w = (const float*)d_in[8];  const float* f1b = (const float*)d_in[9];
    const float* f2w = (const float*)d_in[10]; const float* f2b = (const float*)d_in[11];
    const float* f3w = (const float*)d_in[12]; const float* f3b = (const float*)d_in[13];
    const float* f4w = (const float*)d_in[14]; const float* f4b = (const float*)d_in[15];
    float* out = (float*)d_out;

    cudaFuncSetAttribute(k3_mma, cudaFuncAttributeMaxDynamicSharedMemorySize, K3_SMEM);

    k1_pre<<<1880, 128>>>(emb, edges, w1, b1);
    k2_feat<<<2048, 128>>>(w2, b2, w3, b3);
    k3_mma<<<148, 256, K3_SMEM>>>(f1w, f1b, f2w, f2b, f3w, f3b, f4w, f4b);
    k4_prop<<<1024, 256>>>(edges);
    k5_norm<<<1, 1024>>>(out);
}